// round 14
// baseline (speedup 1.0000x reference)
#include <cuda_runtime.h>
#include <cuda_fp16.h>

#define NN   80000
#define EE   1280000
#define ET   (EE + NN)
#define HH   64
#define FIND 128
#define OUTD 10

// ---------------- scratch ----------------
__device__ __half g_xl[(size_t)NN * HH];   // fp16: halves per-edge gather traffic
__device__ float  g_xr[(size_t)NN * HH];
__device__ float  g_h1[(size_t)NN * HH];
__device__ float  g_h2[(size_t)NN * HH];
__device__ int    g_deg[NN];
__device__ int    g_off[NN + 1];
__device__ int    g_cur[NN];
__device__ int    g_src[ET];
__device__ int    g_bsum[128];

// ---------------- CSR build ----------------
__global__ void count_kernel(const int* __restrict__ ei) {
    int i = blockIdx.x * blockDim.x + threadIdx.x;
    if (i < ET) {
        int d = (i < EE) ? ei[EE + i] : (i - EE);
        atomicAdd(&g_deg[d], 1);
    }
}

__global__ __launch_bounds__(1024) void block_scan_kernel() {
    __shared__ int wsum[32];
    int lane = threadIdx.x & 31, wid = threadIdx.x >> 5;
    int i = blockIdx.x * 1024 + threadIdx.x;
    int v = (i < NN) ? g_deg[i] : 0;
    int x = v;
    #pragma unroll
    for (int d = 1; d < 32; d <<= 1) {
        int y = __shfl_up_sync(0xffffffffu, x, d);
        if (lane >= d) x += y;
    }
    if (lane == 31) wsum[wid] = x;
    __syncthreads();
    if (wid == 0) {
        int s = wsum[lane];
        #pragma unroll
        for (int d = 1; d < 32; d <<= 1) {
            int y = __shfl_up_sync(0xffffffffu, s, d);
            if (lane >= d) s += y;
        }
        wsum[lane] = s;
    }
    __syncthreads();
    int pre = wid ? wsum[wid - 1] : 0;
    if (i < NN) g_off[i] = pre + x - v;
    if (threadIdx.x == 1023) g_bsum[blockIdx.x] = pre + x;
}

__global__ __launch_bounds__(1024) void add_offsets_kernel() {
    __shared__ int pre;
    int bid = blockIdx.x;
    if (threadIdx.x < 32) {
        int s = 0;
        for (int i = threadIdx.x; i < bid; i += 32) s += g_bsum[i];
        #pragma unroll
        for (int o = 16; o; o >>= 1) s += __shfl_xor_sync(0xffffffffu, s, o);
        if (threadIdx.x == 0) pre = s;
    }
    __syncthreads();
    int i = bid * 1024 + threadIdx.x;
    if (i < NN) {
        int o = g_off[i] + pre;
        g_off[i] = o;
        g_cur[i] = o;
    }
    if (i == 0) g_off[NN] = ET;
}

__global__ void scatter_kernel(const int* __restrict__ ei) {
    int i = blockIdx.x * blockDim.x + threadIdx.x;
    if (i < ET) {
        int s, d;
        if (i < EE) { s = ei[i]; d = ei[EE + i]; }
        else        { s = i - EE; d = s; }
        int p = atomicAdd(&g_cur[d], 1);
        g_src[p] = s;
    }
}

// ---------------- tf32 tensor-core dual projection ----------------
// A fragments loaded DIRECTLY to registers (no smem staging: zero cross-warp
// reuse of A, so the old As tile was pure overhead). W staged via smem (8x reuse).
__device__ __forceinline__ unsigned f2tf(float v) {
    unsigned u;
    asm("cvt.rna.tf32.f32 %0, %1;" : "=r"(u) : "f"(v));
    return u;
}

__global__ __launch_bounds__(256) void dual_linear_tc(
    const float* __restrict__ A, int fin,
    const float* __restrict__ Wl, const float* __restrict__ bl,
    const float* __restrict__ Wr, const float* __restrict__ br)
{
    __shared__ unsigned Blf[8 * 4 * 32 * 2];   // 8KB [n][s][lane][2]
    __shared__ unsigned Brf[8 * 4 * 32 * 2];   // 8KB

    const int t    = threadIdx.x;
    const int lane = t & 31;
    const int w    = t >> 5;
    const int n0   = blockIdx.x * 128;

    float accl[8][4], accr[8][4];
    #pragma unroll
    for (int n = 0; n < 8; n++)
        #pragma unroll
        for (int j = 0; j < 4; j++) { accl[n][j] = 0.f; accr[n][j] = 0.f; }

    // A fragment addressing (m16n8k8 tf32): r = lane>>2, c = lane&3
    const int arow = n0 + w * 16 + (lane >> 2);
    const int acol = lane & 3;
    const float* Alo = A + (size_t)arow * fin + acol;
    const float* Ahi = Alo + (size_t)8 * fin;

    const int wh = t & 63;
    const int wq = t >> 6;

    for (int kc = 0; kc < fin; kc += 32) {
        // ---- stage W chunks into fragment layout ----
        #pragma unroll
        for (int part = 0; part < 2; part++) {
            int kb = wq * 8 + part * 4;
            const float4 v = *(const float4*)(Wl + (size_t)wh * fin + kc + kb);
            const float4 u = *(const float4*)(Wr + (size_t)wh * fin + kc + kb);
            float vl[4] = {v.x, v.y, v.z, v.w};
            float vr[4] = {u.x, u.y, u.z, u.w};
            int nt = wh >> 3;
            #pragma unroll
            for (int cc = 0; cc < 4; cc++) {
                int k  = kb + cc;
                int s  = k >> 3;
                int j  = ((k & 7) >= 4) ? 1 : 0;
                int ln = (wh & 7) * 4 + (k & 3);
                int idx = (((nt * 4 + s) * 32) + ln) * 2 + j;
                Blf[idx] = f2tf(vl[cc]);
                Brf[idx] = f2tf(vr[cc]);
            }
        }
        __syncthreads();

        #pragma unroll
        for (int s = 0; s < 4; s++) {
            int k0 = kc + s * 8;
            uint4 a;
            a.x = f2tf(Alo[k0]);
            a.y = f2tf(Ahi[k0]);
            a.z = f2tf(Alo[k0 + 4]);
            a.w = f2tf(Ahi[k0 + 4]);
            #pragma unroll
            for (int n = 0; n < 8; n++) {
                uint2 b = *(const uint2*)(Blf + (((n * 4 + s) * 32) + lane) * 2);
                asm volatile(
                    "mma.sync.aligned.m16n8k8.row.col.f32.tf32.tf32.f32 "
                    "{%0,%1,%2,%3}, {%4,%5,%6,%7}, {%8,%9}, {%0,%1,%2,%3};"
                    : "+f"(accl[n][0]), "+f"(accl[n][1]), "+f"(accl[n][2]), "+f"(accl[n][3])
                    : "r"(a.x), "r"(a.y), "r"(a.z), "r"(a.w), "r"(b.x), "r"(b.y));
                uint2 c = *(const uint2*)(Brf + (((n * 4 + s) * 32) + lane) * 2);
                asm volatile(
                    "mma.sync.aligned.m16n8k8.row.col.f32.tf32.tf32.f32 "
                    "{%0,%1,%2,%3}, {%4,%5,%6,%7}, {%8,%9}, {%0,%1,%2,%3};"
                    : "+f"(accr[n][0]), "+f"(accr[n][1]), "+f"(accr[n][2]), "+f"(accr[n][3])
                    : "r"(a.x), "r"(a.y), "r"(a.z), "r"(a.w), "r"(c.x), "r"(c.y));
            }
        }
        __syncthreads();
    }

    // epilogue: xl -> fp16, xr -> fp32
    int r0 = n0 + w * 16 + (lane >> 2);
    int cq = (lane & 3) * 2;
    #pragma unroll
    for (int n = 0; n < 8; n++) {
        int col = n * 8 + cq;
        float2 bl2 = *(const float2*)(bl + col);
        float2 br2 = *(const float2*)(br + col);
        *(__half2*)(g_xl + (size_t)r0 * HH + col) =
            __floats2half2_rn(accl[n][0] + bl2.x, accl[n][1] + bl2.y);
        *(__half2*)(g_xl + (size_t)(r0 + 8) * HH + col) =
            __floats2half2_rn(accl[n][2] + bl2.x, accl[n][3] + bl2.y);
        float2 o;
        o.x = accr[n][0] + br2.x; o.y = accr[n][1] + br2.y;
        *(float2*)(g_xr + (size_t)r0 * HH + col) = o;
        o.x = accr[n][2] + br2.x; o.y = accr[n][3] + br2.y;
        *(float2*)(g_xr + (size_t)(r0 + 8) * HH + col) = o;
    }
}

// ---------------- half-warp-per-node edge pass: fp16 gather, no-max softmax, ex2 ----
__device__ __forceinline__ float ex2f(float v) {
    float r;
    asm("ex2.approx.f32 %0, %1;" : "=f"(r) : "f"(v));
    return r;
}

template <bool FINAL>
__global__ __launch_bounds__(256) void gat_edge_half(
    const float* __restrict__ att, const float* __restrict__ b,
    float* __restrict__ hout,
    const float* __restrict__ Wro, const float* __restrict__ bro,
    float* __restrict__ out)
{
    __shared__ float Ws[OUTD * HH];
    if (FINAL) {
        for (int i = threadIdx.x; i < OUTD * HH; i += blockDim.x) Ws[i] = Wro[i];
        __syncthreads();
    }

    int lane = threadIdx.x & 31;
    int half = lane >> 4;
    int sl   = lane & 15;
    unsigned hm = 0xFFFFu << (half * 16);

    int node = (blockIdx.x * (blockDim.x >> 5) + (threadIdx.x >> 5)) * 2 + half;
    if (node >= NN) return;

    const float L2E = 1.4426950408889634f;
    float4 att4 = *(const float4*)(att + 4 * sl);
    att4.x *= L2E; att4.y *= L2E; att4.z *= L2E; att4.w *= L2E;
    const float4 xr4 = *(const float4*)(g_xr + (size_t)node * HH + 4 * sl);

    int s = g_off[node], e = g_off[node + 1];

    float d = 0.f;
    float4 acc = make_float4(0.f, 0.f, 0.f, 0.f);

    for (int i = s; i < e; i += 4) {
        uint2  raw[4];
        float4 a[4];
        float  p[4];
        #pragma unroll
        for (int j = 0; j < 4; j++) {
            int src = (i + j < e) ? __ldg(g_src + i + j) : node;
            raw[j] = *(const uint2*)(g_xl + (size_t)src * HH + 4 * sl);  // 8B: 4 halves
        }
        #pragma unroll
        for (int j = 0; j < 4; j++) {
            float2 f01 = __half22float2(*(__half2*)&raw[j].x);
            float2 f23 = __half22float2(*(__half2*)&raw[j].y);
            a[j] = make_float4(f01.x, f01.y, f23.x, f23.y);
            float t0 = a[j].x + xr4.x; t0 = t0 > 0.f ? t0 : 0.2f * t0;
            float t1 = a[j].y + xr4.y; t1 = t1 > 0.f ? t1 : 0.2f * t1;
            float t2 = a[j].z + xr4.z; t2 = t2 > 0.f ? t2 : 0.2f * t2;
            float t3 = a[j].w + xr4.w; t3 = t3 > 0.f ? t3 : 0.2f * t3;
            p[j] = t0 * att4.x + t1 * att4.y + t2 * att4.z + t3 * att4.w;
        }
        #pragma unroll
        for (int o = 8; o; o >>= 1) {
            #pragma unroll
            for (int j = 0; j < 4; j++)
                p[j] += __shfl_xor_sync(hm, p[j], o, 16);
        }
        #pragma unroll
        for (int j = 0; j < 4; j++) {
            float w = (i + j < e) ? ex2f(p[j]) : 0.f;
            d += w;
            acc.x += w * a[j].x; acc.y += w * a[j].y;
            acc.z += w * a[j].z; acc.w += w * a[j].w;
        }
    }

    float inv = __fdividef(1.f, d);
    const float4 b4 = *(const float4*)(b + 4 * sl);
    float4 o4;
    o4.x = fmaxf(acc.x * inv + b4.x, 0.f);
    o4.y = fmaxf(acc.y * inv + b4.y, 0.f);
    o4.z = fmaxf(acc.z * inv + b4.z, 0.f);
    o4.w = fmaxf(acc.w * inv + b4.w, 0.f);

    if (!FINAL) {
        *(float4*)(hout + (size_t)node * HH + 4 * sl) = o4;
    } else {
        #pragma unroll
        for (int o = 0; o < OUTD; o++) {
            const float4 w4 = *(const float4*)(Ws + o * HH + 4 * sl);
            float q = o4.x * w4.x + o4.y * w4.y + o4.z * w4.z + o4.w * w4.w;
            #pragma unroll
            for (int r = 8; r; r >>= 1) q += __shfl_xor_sync(hm, q, r, 16);
            if (sl == 0) out[(size_t)node * OUTD + o] = q + __ldg(bro + o);
        }
    }
}

// ---------------- launch ----------------
extern "C" void kernel_launch(void* const* d_in, const int* in_sizes, int n_in,
                              void* d_out, int out_size)
{
    const float* x  = (const float*)d_in[0];
    const int*   ei = (const int*)d_in[1];
    const float* Wl0 = (const float*)d_in[3];
    const float* bl0 = (const float*)d_in[4];
    const float* Wr0 = (const float*)d_in[5];
    const float* br0 = (const float*)d_in[6];
    const float* at0 = (const float*)d_in[7];
    const float* b0  = (const float*)d_in[8];
    const float* Wl1 = (const float*)d_in[9];
    const float* bl1 = (const float*)d_in[10];
    const float* Wr1 = (const float*)d_in[11];
    const float* br1 = (const float*)d_in[12];
    const float* at1 = (const float*)d_in[13];
    const float* b1  = (const float*)d_in[14];
    const float* Wl2 = (const float*)d_in[15];
    const float* bl2 = (const float*)d_in[16];
    const float* Wr2 = (const float*)d_in[17];
    const float* br2 = (const float*)d_in[18];
    const float* at2 = (const float*)d_in[19];
    const float* b2  = (const float*)d_in[20];
    const float* Wro = (const float*)d_in[21];
    const float* bro = (const float*)d_in[22];
    float* out = (float*)d_out;

    float *h1p, *h2p;
    void  *degp;
    cudaGetSymbolAddress((void**)&h1p, g_h1);
    cudaGetSymbolAddress((void**)&h2p, g_h2);
    cudaGetSymbolAddress(&degp, g_deg);

    const int NB = (NN + 1023) / 1024;   // 79 scan blocks
    const int GB = NN / 128;             // 625 GEMM blocks
    const int EB = NN / 16;              // 5000 edge blocks

    cudaMemsetAsync(degp, 0, NN * sizeof(int));
    count_kernel<<<(ET + 255) / 256, 256>>>(ei);
    block_scan_kernel<<<NB, 1024>>>();
    add_offsets_kernel<<<NB, 1024>>>();
    scatter_kernel<<<(ET + 255) / 256, 256>>>(ei);

    dual_linear_tc<<<GB, 256>>>(x, FIND, Wl0, bl0, Wr0, br0);
    gat_edge_half<false><<<EB, 256>>>(at0, b0, h1p, nullptr, nullptr, nullptr);
    dual_linear_tc<<<GB, 256>>>(h1p, HH, Wl1, bl1, Wr1, br1);
    gat_edge_half<false><<<EB, 256>>>(at1, b1, h2p, nullptr, nullptr, nullptr);
    dual_linear_tc<<<GB, 256>>>(h2p, HH, Wl2, bl2, Wr2, br2);
    gat_edge_half<true><<<EB, 256>>>(at2, b2, nullptr, Wro, bro, out);
}

// round 15
// speedup vs baseline: 1.0563x; 1.0563x over previous
#include <cuda_runtime.h>
#include <cuda_fp16.h>

#define NN   80000
#define EE   1280000
#define ET   (EE + NN)
#define HH   64
#define FIND 128
#define OUTD 10

// ---------------- scratch ----------------
__device__ __half g_xl[(size_t)NN * HH];   // fp16 edge-gather operand
__device__ float  g_xr[(size_t)NN * HH];
__device__ __half g_h1[(size_t)NN * HH];   // fp16 hidden activations
__device__ __half g_h2[(size_t)NN * HH];
__device__ int    g_deg[NN];
__device__ int    g_off[NN + 1];
__device__ int    g_cur[NN];
__device__ int    g_src[ET];
__device__ int    g_bsum[128];

// ---------------- CSR build ----------------
__global__ void count_kernel(const int* __restrict__ ei) {
    int i = blockIdx.x * blockDim.x + threadIdx.x;
    if (i < ET) {
        int d = (i < EE) ? ei[EE + i] : (i - EE);
        atomicAdd(&g_deg[d], 1);
    }
}

__global__ __launch_bounds__(1024) void block_scan_kernel() {
    __shared__ int wsum[32];
    int lane = threadIdx.x & 31, wid = threadIdx.x >> 5;
    int i = blockIdx.x * 1024 + threadIdx.x;
    int v = (i < NN) ? g_deg[i] : 0;
    int x = v;
    #pragma unroll
    for (int d = 1; d < 32; d <<= 1) {
        int y = __shfl_up_sync(0xffffffffu, x, d);
        if (lane >= d) x += y;
    }
    if (lane == 31) wsum[wid] = x;
    __syncthreads();
    if (wid == 0) {
        int s = wsum[lane];
        #pragma unroll
        for (int d = 1; d < 32; d <<= 1) {
            int y = __shfl_up_sync(0xffffffffu, s, d);
            if (lane >= d) s += y;
        }
        wsum[lane] = s;
    }
    __syncthreads();
    int pre = wid ? wsum[wid - 1] : 0;
    if (i < NN) g_off[i] = pre + x - v;
    if (threadIdx.x == 1023) g_bsum[blockIdx.x] = pre + x;
}

__global__ __launch_bounds__(1024) void add_offsets_kernel() {
    __shared__ int pre;
    int bid = blockIdx.x;
    if (threadIdx.x < 32) {
        int s = 0;
        for (int i = threadIdx.x; i < bid; i += 32) s += g_bsum[i];
        #pragma unroll
        for (int o = 16; o; o >>= 1) s += __shfl_xor_sync(0xffffffffu, s, o);
        if (threadIdx.x == 0) pre = s;
    }
    __syncthreads();
    int i = bid * 1024 + threadIdx.x;
    if (i < NN) {
        int o = g_off[i] + pre;
        g_off[i] = o;
        g_cur[i] = o;
    }
    if (i == 0) g_off[NN] = ET;
}

__global__ void scatter_kernel(const int* __restrict__ ei) {
    int i = blockIdx.x * blockDim.x + threadIdx.x;
    if (i < ET) {
        int s, d;
        if (i < EE) { s = ei[i]; d = ei[EE + i]; }
        else        { s = i - EE; d = s; }
        int p = atomicAdd(&g_cur[d], 1);
        g_src[p] = s;
    }
}

// ---------------- fp16 tensor-core dual projection (m16n8k16) ----------------
// D(l,r)[128x64] = A[128xK] @ W(l,r)^T.  B (weights) staged to smem in exact
// fragment layout; A fragments loaded directly from global (no cross-warp reuse).
// m16n8k16 fragment map (lane g = lane>>2, tid = lane&3):
//   A: a0=A[g][t2,t2+1]  a1=A[g+8][t2..]  a2=A[g][t2+8..]  a3=A[g+8][t2+8..]   (t2=tid*2)
//   B: b0=W[n0+g][t2,t2+1]               b1=W[n0+g][t2+8,t2+9]
//   D: d0,d1=row g cols tid*2,+1 ; d2,d3=row g+8  (same as before)

template <typename AT>
__device__ __forceinline__ unsigned load_a_half2(const AT* p);

template <>
__device__ __forceinline__ unsigned load_a_half2<float>(const float* p) {
    float2 f = *(const float2*)p;
    __half2 h = __floats2half2_rn(f.x, f.y);
    return *(unsigned*)&h;
}
template <>
__device__ __forceinline__ unsigned load_a_half2<__half>(const __half* p) {
    return *(const unsigned*)p;
}

template <typename AT>
__global__ __launch_bounds__(256) void dual_linear_h(
    const AT* __restrict__ A, int fin,
    const float* __restrict__ Wl, const float* __restrict__ bl,
    const float* __restrict__ Wr, const float* __restrict__ br)
{
    // [ntile(8)][sc(2)][lane(32)] x uint2 (b0,b1) = 4KB each
    __shared__ unsigned Blf[8 * 2 * 32 * 2];
    __shared__ unsigned Brf[8 * 2 * 32 * 2];

    const int t    = threadIdx.x;
    const int lane = t & 31;
    const int w    = t >> 5;
    const int n0   = blockIdx.x * 128;

    float accl[8][4], accr[8][4];
    #pragma unroll
    for (int n = 0; n < 8; n++)
        #pragma unroll
        for (int j = 0; j < 4; j++) { accl[n][j] = 0.f; accr[n][j] = 0.f; }

    const int arow = n0 + w * 16 + (lane >> 2);
    const AT* Alo = A + (size_t)arow * fin;
    const AT* Ahi = Alo + (size_t)8 * fin;

    const int wh = t & 63;        // W row (h index)
    const int wq = t >> 6;        // k-octet within 32-chunk

    for (int kc = 0; kc < fin; kc += 32) {
        // ---- stage W chunk into fragment layout (half stores) ----
        {
            const float4 v = *(const float4*)(Wl + (size_t)wh * fin + kc + wq * 8);
            const float4 u = *(const float4*)(Wl + (size_t)wh * fin + kc + wq * 8 + 4);
            const float4 v2 = *(const float4*)(Wr + (size_t)wh * fin + kc + wq * 8);
            const float4 u2 = *(const float4*)(Wr + (size_t)wh * fin + kc + wq * 8 + 4);
            float el[8] = {v.x, v.y, v.z, v.w, u.x, u.y, u.z, u.w};
            float er[8] = {v2.x, v2.y, v2.z, v2.w, u2.x, u2.y, u2.z, u2.w};
            int ntile = wh >> 3;
            #pragma unroll
            for (int e = 0; e < 8; e++) {
                int kic  = wq * 8 + e;          // k within 32-chunk
                int sc   = kic >> 4;            // k16-step (0/1)
                int k16  = kic & 15;
                int reg  = (k16 >= 8) ? 1 : 0;  // b0 / b1
                int tid  = (k16 & 7) >> 1;
                int hpos = k16 & 1;
                int ln   = ((wh & 7) << 2) | tid;
                int hidx = ((((ntile * 2 + sc) * 32 + ln) * 2 + reg) << 1) | hpos;
                ((__half*)Blf)[hidx] = __float2half_rn(el[e]);
                ((__half*)Brf)[hidx] = __float2half_rn(er[e]);
            }
        }
        __syncthreads();

        // ---- mma: 2 k16-steps x 8 n-tiles x {l,r} ----
        #pragma unroll
        for (int sc = 0; sc < 2; sc++) {
            int kb = kc + sc * 16 + (lane & 3) * 2;
            unsigned a0 = load_a_half2<AT>(Alo + kb);
            unsigned a1 = load_a_half2<AT>(Ahi + kb);
            unsigned a2 = load_a_half2<AT>(Alo + kb + 8);
            unsigned a3 = load_a_half2<AT>(Ahi + kb + 8);
            #pragma unroll
            for (int n = 0; n < 8; n++) {
                uint2 b = *(const uint2*)(Blf + ((n * 2 + sc) * 32 + lane) * 2);
                asm volatile(
                    "mma.sync.aligned.m16n8k16.row.col.f32.f16.f16.f32 "
                    "{%0,%1,%2,%3}, {%4,%5,%6,%7}, {%8,%9}, {%0,%1,%2,%3};"
                    : "+f"(accl[n][0]), "+f"(accl[n][1]), "+f"(accl[n][2]), "+f"(accl[n][3])
                    : "r"(a0), "r"(a1), "r"(a2), "r"(a3), "r"(b.x), "r"(b.y));
                uint2 c = *(const uint2*)(Brf + ((n * 2 + sc) * 32 + lane) * 2);
                asm volatile(
                    "mma.sync.aligned.m16n8k16.row.col.f32.f16.f16.f32 "
                    "{%0,%1,%2,%3}, {%4,%5,%6,%7}, {%8,%9}, {%0,%1,%2,%3};"
                    : "+f"(accr[n][0]), "+f"(accr[n][1]), "+f"(accr[n][2]), "+f"(accr[n][3])
                    : "r"(a0), "r"(a1), "r"(a2), "r"(a3), "r"(c.x), "r"(c.y));
            }
        }
        __syncthreads();
    }

    // epilogue: xl -> fp16, xr -> fp32
    int r0 = n0 + w * 16 + (lane >> 2);
    int cq = (lane & 3) * 2;
    #pragma unroll
    for (int n = 0; n < 8; n++) {
        int col = n * 8 + cq;
        float2 bl2 = *(const float2*)(bl + col);
        float2 br2 = *(const float2*)(br + col);
        *(__half2*)(g_xl + (size_t)r0 * HH + col) =
            __floats2half2_rn(accl[n][0] + bl2.x, accl[n][1] + bl2.y);
        *(__half2*)(g_xl + (size_t)(r0 + 8) * HH + col) =
            __floats2half2_rn(accl[n][2] + bl2.x, accl[n][3] + bl2.y);
        float2 o;
        o.x = accr[n][0] + br2.x; o.y = accr[n][1] + br2.y;
        *(float2*)(g_xr + (size_t)r0 * HH + col) = o;
        o.x = accr[n][2] + br2.x; o.y = accr[n][3] + br2.y;
        *(float2*)(g_xr + (size_t)(r0 + 8) * HH + col) = o;
    }
}

// ---------------- half-warp-per-node edge pass: fp16 gather, no-max softmax, ex2 ----
__device__ __forceinline__ float ex2f(float v) {
    float r;
    asm("ex2.approx.f32 %0, %1;" : "=f"(r) : "f"(v));
    return r;
}

template <bool FINAL>
__global__ __launch_bounds__(256) void gat_edge_half(
    const float* __restrict__ att, const float* __restrict__ b,
    __half* __restrict__ hout,
    const float* __restrict__ Wro, const float* __restrict__ bro,
    float* __restrict__ out)
{
    __shared__ float Ws[OUTD * HH];
    if (FINAL) {
        for (int i = threadIdx.x; i < OUTD * HH; i += blockDim.x) Ws[i] = Wro[i];
        __syncthreads();
    }

    int lane = threadIdx.x & 31;
    int half = lane >> 4;
    int sl   = lane & 15;
    unsigned hm = 0xFFFFu << (half * 16);

    int node = (blockIdx.x * (blockDim.x >> 5) + (threadIdx.x >> 5)) * 2 + half;
    if (node >= NN) return;

    const float L2E = 1.4426950408889634f;
    float4 att4 = *(const float4*)(att + 4 * sl);
    att4.x *= L2E; att4.y *= L2E; att4.z *= L2E; att4.w *= L2E;
    const float4 xr4 = *(const float4*)(g_xr + (size_t)node * HH + 4 * sl);

    int s = g_off[node], e = g_off[node + 1];

    float d = 0.f;
    float4 acc = make_float4(0.f, 0.f, 0.f, 0.f);

    for (int i = s; i < e; i += 4) {
        uint2  raw[4];
        float4 a[4];
        float  p[4];
        #pragma unroll
        for (int j = 0; j < 4; j++) {
            int src = (i + j < e) ? __ldg(g_src + i + j) : node;
            raw[j] = *(const uint2*)(g_xl + (size_t)src * HH + 4 * sl);
        }
        #pragma unroll
        for (int j = 0; j < 4; j++) {
            float2 f01 = __half22float2(*(__half2*)&raw[j].x);
            float2 f23 = __half22float2(*(__half2*)&raw[j].y);
            a[j] = make_float4(f01.x, f01.y, f23.x, f23.y);
            float t0 = a[j].x + xr4.x; t0 = t0 > 0.f ? t0 : 0.2f * t0;
            float t1 = a[j].y + xr4.y; t1 = t1 > 0.f ? t1 : 0.2f * t1;
            float t2 = a[j].z + xr4.z; t2 = t2 > 0.f ? t2 : 0.2f * t2;
            float t3 = a[j].w + xr4.w; t3 = t3 > 0.f ? t3 : 0.2f * t3;
            p[j] = t0 * att4.x + t1 * att4.y + t2 * att4.z + t3 * att4.w;
        }
        #pragma unroll
        for (int o = 8; o; o >>= 1) {
            #pragma unroll
            for (int j = 0; j < 4; j++)
                p[j] += __shfl_xor_sync(hm, p[j], o, 16);
        }
        #pragma unroll
        for (int j = 0; j < 4; j++) {
            float w = (i + j < e) ? ex2f(p[j]) : 0.f;
            d += w;
            acc.x += w * a[j].x; acc.y += w * a[j].y;
            acc.z += w * a[j].z; acc.w += w * a[j].w;
        }
    }

    float inv = __fdividef(1.f, d);
    const float4 b4 = *(const float4*)(b + 4 * sl);
    float4 o4;
    o4.x = fmaxf(acc.x * inv + b4.x, 0.f);
    o4.y = fmaxf(acc.y * inv + b4.y, 0.f);
    o4.z = fmaxf(acc.z * inv + b4.z, 0.f);
    o4.w = fmaxf(acc.w * inv + b4.w, 0.f);

    if (!FINAL) {
        uint2 packed;
        __half2 h01 = __floats2half2_rn(o4.x, o4.y);
        __half2 h23 = __floats2half2_rn(o4.z, o4.w);
        packed.x = *(unsigned*)&h01;
        packed.y = *(unsigned*)&h23;
        *(uint2*)(hout + (size_t)node * HH + 4 * sl) = packed;
    } else {
        #pragma unroll
        for (int o = 0; o < OUTD; o++) {
            const float4 w4 = *(const float4*)(Ws + o * HH + 4 * sl);
            float q = o4.x * w4.x + o4.y * w4.y + o4.z * w4.z + o4.w * w4.w;
            #pragma unroll
            for (int r = 8; r; r >>= 1) q += __shfl_xor_sync(hm, q, r, 16);
            if (sl == 0) out[(size_t)node * OUTD + o] = q + __ldg(bro + o);
        }
    }
}

// ---------------- launch ----------------
extern "C" void kernel_launch(void* const* d_in, const int* in_sizes, int n_in,
                              void* d_out, int out_size)
{
    const float* x  = (const float*)d_in[0];
    const int*   ei = (const int*)d_in[1];
    const float* Wl0 = (const float*)d_in[3];
    const float* bl0 = (const float*)d_in[4];
    const float* Wr0 = (const float*)d_in[5];
    const float* br0 = (const float*)d_in[6];
    const float* at0 = (const float*)d_in[7];
    const float* b0  = (const float*)d_in[8];
    const float* Wl1 = (const float*)d_in[9];
    const float* bl1 = (const float*)d_in[10];
    const float* Wr1 = (const float*)d_in[11];
    const float* br1 = (const float*)d_in[12];
    const float* at1 = (const float*)d_in[13];
    const float* b1  = (const float*)d_in[14];
    const float* Wl2 = (const float*)d_in[15];
    const float* bl2 = (const float*)d_in[16];
    const float* Wr2 = (const float*)d_in[17];
    const float* br2 = (const float*)d_in[18];
    const float* at2 = (const float*)d_in[19];
    const float* b2  = (const float*)d_in[20];
    const float* Wro = (const float*)d_in[21];
    const float* bro = (const float*)d_in[22];
    float* out = (float*)d_out;

    __half *h1p, *h2p;
    void   *degp;
    cudaGetSymbolAddress((void**)&h1p, g_h1);
    cudaGetSymbolAddress((void**)&h2p, g_h2);
    cudaGetSymbolAddress(&degp, g_deg);

    const int NB = (NN + 1023) / 1024;   // 79 scan blocks
    const int GB = NN / 128;             // 625 GEMM blocks
    const int EB = NN / 16;              // 5000 edge blocks

    cudaMemsetAsync(degp, 0, NN * sizeof(int));
    count_kernel<<<(ET + 255) / 256, 256>>>(ei);
    block_scan_kernel<<<NB, 1024>>>();
    add_offsets_kernel<<<NB, 1024>>>();
    scatter_kernel<<<(ET + 255) / 256, 256>>>(ei);

    dual_linear_h<float><<<GB, 256>>>(x, FIND, Wl0, bl0, Wr0, br0);
    gat_edge_half<false><<<EB, 256>>>(at0, b0, h1p, nullptr, nullptr, nullptr);
    dual_linear_h<__half><<<GB, 256>>>(h1p, HH, Wl1, bl1, Wr1, br1);
    gat_edge_half<false><<<EB, 256>>>(at1, b1, h2p, nullptr, nullptr, nullptr);
    dual_linear_h<__half><<<GB, 256>>>(h2p, HH, Wl2, bl2, Wr2, br2);
    gat_edge_half<true><<<EB, 256>>>(at2, b2, nullptr, Wro, bro, out);
}

// round 16
// speedup vs baseline: 1.1341x; 1.0736x over previous
#include <cuda_runtime.h>
#include <cuda_fp16.h>

#define NN   80000
#define EE   1280000
#define ET   (EE + NN)
#define HH   64
#define FIND 128
#define OUTD 10

// ---------------- scratch ----------------
__device__ __half g_xl[(size_t)NN * HH];   // fp16 edge-gather operand
__device__ float  g_xr[(size_t)NN * HH];
__device__ __half g_h1[(size_t)NN * HH];   // fp16 hidden activations
__device__ __half g_h2[(size_t)NN * HH];
__device__ int    g_deg[NN];
__device__ int    g_off[NN + 1];
__device__ int    g_cur[NN];
__device__ int    g_src[ET];
__device__ int    g_bsum[128];

// ---------------- CSR build ----------------
__global__ void count_kernel(const int* __restrict__ ei) {
    int i = blockIdx.x * blockDim.x + threadIdx.x;
    if (i < ET) {
        int d = (i < EE) ? ei[EE + i] : (i - EE);
        atomicAdd(&g_deg[d], 1);
    }
}

__global__ __launch_bounds__(1024) void block_scan_kernel() {
    __shared__ int wsum[32];
    int lane = threadIdx.x & 31, wid = threadIdx.x >> 5;
    int i = blockIdx.x * 1024 + threadIdx.x;
    int v = (i < NN) ? g_deg[i] : 0;
    int x = v;
    #pragma unroll
    for (int d = 1; d < 32; d <<= 1) {
        int y = __shfl_up_sync(0xffffffffu, x, d);
        if (lane >= d) x += y;
    }
    if (lane == 31) wsum[wid] = x;
    __syncthreads();
    if (wid == 0) {
        int s = wsum[lane];
        #pragma unroll
        for (int d = 1; d < 32; d <<= 1) {
            int y = __shfl_up_sync(0xffffffffu, s, d);
            if (lane >= d) s += y;
        }
        wsum[lane] = s;
    }
    __syncthreads();
    int pre = wid ? wsum[wid - 1] : 0;
    if (i < NN) g_off[i] = pre + x - v;
    if (threadIdx.x == 1023) g_bsum[blockIdx.x] = pre + x;
}

__global__ __launch_bounds__(1024) void add_offsets_kernel() {
    __shared__ int pre;
    int bid = blockIdx.x;
    if (threadIdx.x < 32) {
        int s = 0;
        for (int i = threadIdx.x; i < bid; i += 32) s += g_bsum[i];
        #pragma unroll
        for (int o = 16; o; o >>= 1) s += __shfl_xor_sync(0xffffffffu, s, o);
        if (threadIdx.x == 0) pre = s;
    }
    __syncthreads();
    int i = bid * 1024 + threadIdx.x;
    if (i < NN) {
        int o = g_off[i] + pre;
        g_off[i] = o;
        g_cur[i] = o;
    }
    if (i == 0) g_off[NN] = ET;
}

__global__ void scatter_kernel(const int* __restrict__ ei) {
    int i = blockIdx.x * blockDim.x + threadIdx.x;
    if (i < ET) {
        int s, d;
        if (i < EE) { s = ei[i]; d = ei[EE + i]; }
        else        { s = i - EE; d = s; }
        int p = atomicAdd(&g_cur[d], 1);
        g_src[p] = s;
    }
}

// ---------------- fp16 tensor-core dual projection (m16n8k16) ----------------
template <typename AT>
__device__ __forceinline__ unsigned load_a_half2(const AT* p);

template <>
__device__ __forceinline__ unsigned load_a_half2<float>(const float* p) {
    float2 f = *(const float2*)p;
    __half2 h = __floats2half2_rn(f.x, f.y);
    return *(unsigned*)&h;
}
template <>
__device__ __forceinline__ unsigned load_a_half2<__half>(const __half* p) {
    return *(const unsigned*)p;
}

template <typename AT>
__global__ __launch_bounds__(256) void dual_linear_h(
    const AT* __restrict__ A, int fin,
    const float* __restrict__ Wl, const float* __restrict__ bl,
    const float* __restrict__ Wr, const float* __restrict__ br)
{
    __shared__ unsigned Blf[8 * 2 * 32 * 2];   // 4KB
    __shared__ unsigned Brf[8 * 2 * 32 * 2];   // 4KB

    const int t    = threadIdx.x;
    const int lane = t & 31;
    const int w    = t >> 5;
    const int n0   = blockIdx.x * 128;

    float accl[8][4], accr[8][4];
    #pragma unroll
    for (int n = 0; n < 8; n++)
        #pragma unroll
        for (int j = 0; j < 4; j++) { accl[n][j] = 0.f; accr[n][j] = 0.f; }

    const int arow = n0 + w * 16 + (lane >> 2);
    const AT* Alo = A + (size_t)arow * fin;
    const AT* Ahi = Alo + (size_t)8 * fin;

    const int wh = t & 63;
    const int wq = t >> 6;

    for (int kc = 0; kc < fin; kc += 32) {
        {
            const float4 v = *(const float4*)(Wl + (size_t)wh * fin + kc + wq * 8);
            const float4 u = *(const float4*)(Wl + (size_t)wh * fin + kc + wq * 8 + 4);
            const float4 v2 = *(const float4*)(Wr + (size_t)wh * fin + kc + wq * 8);
            const float4 u2 = *(const float4*)(Wr + (size_t)wh * fin + kc + wq * 8 + 4);
            float el[8] = {v.x, v.y, v.z, v.w, u.x, u.y, u.z, u.w};
            float er[8] = {v2.x, v2.y, v2.z, v2.w, u2.x, u2.y, u2.z, u2.w};
            int ntile = wh >> 3;
            #pragma unroll
            for (int e = 0; e < 8; e++) {
                int kic  = wq * 8 + e;
                int sc   = kic >> 4;
                int k16  = kic & 15;
                int reg  = (k16 >= 8) ? 1 : 0;
                int tid  = (k16 & 7) >> 1;
                int hpos = k16 & 1;
                int ln   = ((wh & 7) << 2) | tid;
                int hidx = ((((ntile * 2 + sc) * 32 + ln) * 2 + reg) << 1) | hpos;
                ((__half*)Blf)[hidx] = __float2half_rn(el[e]);
                ((__half*)Brf)[hidx] = __float2half_rn(er[e]);
            }
        }
        __syncthreads();

        #pragma unroll
        for (int sc = 0; sc < 2; sc++) {
            int kb = kc + sc * 16 + (lane & 3) * 2;
            unsigned a0 = load_a_half2<AT>(Alo + kb);
            unsigned a1 = load_a_half2<AT>(Ahi + kb);
            unsigned a2 = load_a_half2<AT>(Alo + kb + 8);
            unsigned a3 = load_a_half2<AT>(Ahi + kb + 8);
            #pragma unroll
            for (int n = 0; n < 8; n++) {
                uint2 b = *(const uint2*)(Blf + ((n * 2 + sc) * 32 + lane) * 2);
                asm volatile(
                    "mma.sync.aligned.m16n8k16.row.col.f32.f16.f16.f32 "
                    "{%0,%1,%2,%3}, {%4,%5,%6,%7}, {%8,%9}, {%0,%1,%2,%3};"
                    : "+f"(accl[n][0]), "+f"(accl[n][1]), "+f"(accl[n][2]), "+f"(accl[n][3])
                    : "r"(a0), "r"(a1), "r"(a2), "r"(a3), "r"(b.x), "r"(b.y));
                uint2 c = *(const uint2*)(Brf + ((n * 2 + sc) * 32 + lane) * 2);
                asm volatile(
                    "mma.sync.aligned.m16n8k16.row.col.f32.f16.f16.f32 "
                    "{%0,%1,%2,%3}, {%4,%5,%6,%7}, {%8,%9}, {%0,%1,%2,%3};"
                    : "+f"(accr[n][0]), "+f"(accr[n][1]), "+f"(accr[n][2]), "+f"(accr[n][3])
                    : "r"(a0), "r"(a1), "r"(a2), "r"(a3), "r"(c.x), "r"(c.y));
            }
        }
        __syncthreads();
    }

    int r0 = n0 + w * 16 + (lane >> 2);
    int cq = (lane & 3) * 2;
    #pragma unroll
    for (int n = 0; n < 8; n++) {
        int col = n * 8 + cq;
        float2 bl2 = *(const float2*)(bl + col);
        float2 br2 = *(const float2*)(br + col);
        *(__half2*)(g_xl + (size_t)r0 * HH + col) =
            __floats2half2_rn(accl[n][0] + bl2.x, accl[n][1] + bl2.y);
        *(__half2*)(g_xl + (size_t)(r0 + 8) * HH + col) =
            __floats2half2_rn(accl[n][2] + bl2.x, accl[n][3] + bl2.y);
        float2 o;
        o.x = accr[n][0] + br2.x; o.y = accr[n][1] + br2.y;
        *(float2*)(g_xr + (size_t)r0 * HH + col) = o;
        o.x = accr[n][2] + br2.x; o.y = accr[n][3] + br2.y;
        *(float2*)(g_xr + (size_t)(r0 + 8) * HH + col) = o;
    }
}

// ---------------- quarter-warp-per-node edge pass ----------------
// 8 lanes per node, 8 dims per lane (fp16 row = 8 x LDG.128). Every warp
// instruction now serves 4 edges; reduction is 3 shuffle steps (width 8).
__device__ __forceinline__ float ex2f(float v) {
    float r;
    asm("ex2.approx.f32 %0, %1;" : "=f"(r) : "f"(v));
    return r;
}

__device__ __forceinline__ void unpack8(uint4 r, float* f) {
    float2 t;
    t = __half22float2(*(__half2*)&r.x); f[0] = t.x; f[1] = t.y;
    t = __half22float2(*(__half2*)&r.y); f[2] = t.x; f[3] = t.y;
    t = __half22float2(*(__half2*)&r.z); f[4] = t.x; f[5] = t.y;
    t = __half22float2(*(__half2*)&r.w); f[6] = t.x; f[7] = t.y;
}

template <bool FINAL>
__global__ __launch_bounds__(256) void gat_edge_q(
    const float* __restrict__ att, const float* __restrict__ b,
    __half* __restrict__ hout,
    const float* __restrict__ Wro, const float* __restrict__ bro,
    float* __restrict__ out)
{
    __shared__ float Ws[OUTD * HH];
    if (FINAL) {
        for (int i = threadIdx.x; i < OUTD * HH; i += blockDim.x) Ws[i] = Wro[i];
        __syncthreads();
    }

    int lane = threadIdx.x & 31;
    int q    = lane >> 3;        // quarter index 0..3
    int sl   = lane & 7;         // lane within quarter
    unsigned hm = 0xFFu << (q * 8);

    int node = (blockIdx.x * (blockDim.x >> 5) + (threadIdx.x >> 5)) * 4 + q;
    if (node >= NN) return;

    const float L2E = 1.4426950408889634f;
    float att8[8], xr8[8];
    *(float4*)(att8)     = *(const float4*)(att + 8 * sl);
    *(float4*)(att8 + 4) = *(const float4*)(att + 8 * sl + 4);
    #pragma unroll
    for (int k = 0; k < 8; k++) att8[k] *= L2E;
    *(float4*)(xr8)      = *(const float4*)(g_xr + (size_t)node * HH + 8 * sl);
    *(float4*)(xr8 + 4)  = *(const float4*)(g_xr + (size_t)node * HH + 8 * sl + 4);

    int s = g_off[node], e = g_off[node + 1];

    float d = 0.f;
    float acc[8];
    #pragma unroll
    for (int k = 0; k < 8; k++) acc[k] = 0.f;

    for (int i = s; i < e; i += 4) {
        uint4 raw[4];
        float p[4];
        #pragma unroll
        for (int j = 0; j < 4; j++) {
            int src = (i + j < e) ? __ldg(g_src + i + j) : node;
            raw[j] = *(const uint4*)(g_xl + (size_t)src * HH + 8 * sl);  // 16B: 8 halves
        }
        #pragma unroll
        for (int j = 0; j < 4; j++) {
            float f[8];
            unpack8(raw[j], f);
            float pj = 0.f;
            #pragma unroll
            for (int k = 0; k < 8; k++) {
                float t = f[k] + xr8[k];
                t = t > 0.f ? t : 0.2f * t;
                pj += t * att8[k];
            }
            p[j] = pj;
        }
        // 4 independent width-8 butterfly chains
        #pragma unroll
        for (int o = 4; o; o >>= 1) {
            #pragma unroll
            for (int j = 0; j < 4; j++)
                p[j] += __shfl_xor_sync(hm, p[j], o, 8);
        }
        #pragma unroll
        for (int j = 0; j < 4; j++) {
            float w = (i + j < e) ? ex2f(p[j]) : 0.f;
            d += w;
            float f[8];
            unpack8(raw[j], f);
            #pragma unroll
            for (int k = 0; k < 8; k++) acc[k] += w * f[k];
        }
    }

    float inv = __fdividef(1.f, d);
    float b8[8];
    *(float4*)(b8)     = *(const float4*)(b + 8 * sl);
    *(float4*)(b8 + 4) = *(const float4*)(b + 8 * sl + 4);
    float o8[8];
    #pragma unroll
    for (int k = 0; k < 8; k++) o8[k] = fmaxf(acc[k] * inv + b8[k], 0.f);

    if (!FINAL) {
        uint4 packed;
        __half2 h01 = __floats2half2_rn(o8[0], o8[1]);
        __half2 h23 = __floats2half2_rn(o8[2], o8[3]);
        __half2 h45 = __floats2half2_rn(o8[4], o8[5]);
        __half2 h67 = __floats2half2_rn(o8[6], o8[7]);
        packed.x = *(unsigned*)&h01;
        packed.y = *(unsigned*)&h23;
        packed.z = *(unsigned*)&h45;
        packed.w = *(unsigned*)&h67;
        *(uint4*)(hout + (size_t)node * HH + 8 * sl) = packed;
    } else {
        #pragma unroll
        for (int o = 0; o < OUTD; o++) {
            const float* wrow = Ws + o * HH + 8 * sl;
            float qv = 0.f;
            #pragma unroll
            for (int k = 0; k < 8; k++) qv += o8[k] * wrow[k];
            #pragma unroll
            for (int r = 4; r; r >>= 1) qv += __shfl_xor_sync(hm, qv, r, 8);
            if (sl == 0) out[(size_t)node * OUTD + o] = qv + __ldg(bro + o);
        }
    }
}

// ---------------- launch ----------------
extern "C" void kernel_launch(void* const* d_in, const int* in_sizes, int n_in,
                              void* d_out, int out_size)
{
    const float* x  = (const float*)d_in[0];
    const int*   ei = (const int*)d_in[1];
    const float* Wl0 = (const float*)d_in[3];
    const float* bl0 = (const float*)d_in[4];
    const float* Wr0 = (const float*)d_in[5];
    const float* br0 = (const float*)d_in[6];
    const float* at0 = (const float*)d_in[7];
    const float* b0  = (const float*)d_in[8];
    const float* Wl1 = (const float*)d_in[9];
    const float* bl1 = (const float*)d_in[10];
    const float* Wr1 = (const float*)d_in[11];
    const float* br1 = (const float*)d_in[12];
    const float* at1 = (const float*)d_in[13];
    const float* b1  = (const float*)d_in[14];
    const float* Wl2 = (const float*)d_in[15];
    const float* bl2 = (const float*)d_in[16];
    const float* Wr2 = (const float*)d_in[17];
    const float* br2 = (const float*)d_in[18];
    const float* at2 = (const float*)d_in[19];
    const float* b2  = (const float*)d_in[20];
    const float* Wro = (const float*)d_in[21];
    const float* bro = (const float*)d_in[22];
    float* out = (float*)d_out;

    __half *h1p, *h2p;
    void   *degp;
    cudaGetSymbolAddress((void**)&h1p, g_h1);
    cudaGetSymbolAddress((void**)&h2p, g_h2);
    cudaGetSymbolAddress(&degp, g_deg);

    const int NB = (NN + 1023) / 1024;   // 79 scan blocks
    const int GB = NN / 128;             // 625 GEMM blocks
    const int EB = NN / 32;              // 2500 edge blocks (32 nodes each)

    cudaMemsetAsync(degp, 0, NN * sizeof(int));
    count_kernel<<<(ET + 255) / 256, 256>>>(ei);
    block_scan_kernel<<<NB, 1024>>>();
    add_offsets_kernel<<<NB, 1024>>>();
    scatter_kernel<<<(ET + 255) / 256, 256>>>(ei);

    dual_linear_h<float><<<GB, 256>>>(x, FIND, Wl0, bl0, Wr0, br0);
    gat_edge_q<false><<<EB, 256>>>(at0, b0, h1p, nullptr, nullptr, nullptr);
    dual_linear_h<__half><<<GB, 256>>>(h1p, HH, Wl1, bl1, Wr1, br1);
    gat_edge_q<false><<<EB, 256>>>(at1, b1, h2p, nullptr, nullptr, nullptr);
    dual_linear_h<__half><<<GB, 256>>>(h2p, HH, Wl2, bl2, Wr2, br2);
    gat_edge_q<true><<<EB, 256>>>(at2, b2, nullptr, Wro, bro, out);
}